// round 15
// baseline (speedup 1.0000x reference)
#include <cuda_runtime.h>
#include <cuda_fp16.h>

#define B_  2
#define L_  2048
#define E_  512
#define H_  8
#define D_  64
#define NC  65
#define KPZ 80         // fp16 K for corr GEMM: [C 65 | pad 15]
#define BH  (B_*H_)

typedef unsigned int uint;

// -------- scratch --------
__device__ __half gCz[(size_t)BH * L_ * KPZ];           // 5.2 MB [bh*L+s][80]
__device__ __half gBz[L_ * KPZ];                        // 0.33 MB [t][80]
__device__ float g_Zp[16 * BH * L_];                    // partial sums (tile-normed)
__device__ float g_E[16 * BH * L_];                     // per (ttile,row) max
__device__ float g_W[16 * BH * L_];                     // e^E * invZ
__device__ __half g_Pf[(size_t)BH * L_ * L_];           // 134 MB [bh][s][t], exp(c-m)

// ---------------- helpers ----------------
__device__ __forceinline__ uint smem_u32(const void* p) {
    uint a;
    asm("{ .reg .u64 t; cvta.to.shared.u64 t, %1; cvt.u32.u64 %0, t; }" : "=r"(a) : "l"(p));
    return a;
}
__device__ __forceinline__ void mma_fp16(float4& c,
                                         uint a0, uint a1, uint a2, uint a3,
                                         uint b0, uint b1) {
    asm volatile(
        "mma.sync.aligned.m16n8k16.row.col.f32.f16.f16.f32 "
        "{%0,%1,%2,%3}, {%4,%5,%6,%7}, {%8,%9}, {%0,%1,%2,%3};"
        : "+f"(c.x), "+f"(c.y), "+f"(c.z), "+f"(c.w)
        : "r"(a0), "r"(a1), "r"(a2), "r"(a3), "r"(b0), "r"(b1));
}
__device__ __forceinline__ void ldsm_x4(uint& r0, uint& r1, uint& r2, uint& r3,
                                        const void* p) {
    uint a = smem_u32(p);
    asm volatile("ldmatrix.sync.aligned.m8n8.x4.shared.b16 {%0,%1,%2,%3}, [%4];"
                 : "=r"(r0), "=r"(r1), "=r"(r2), "=r"(r3) : "r"(a));
}
__device__ __forceinline__ void ldsm_x4_t(uint& r0, uint& r1, uint& r2, uint& r3,
                                          const void* p) {
    uint a = smem_u32(p);
    asm volatile("ldmatrix.sync.aligned.m8n8.x4.trans.shared.b16 {%0,%1,%2,%3}, [%4];"
                 : "=r"(r0), "=r"(r1), "=r"(r2), "=r"(r3) : "r"(a));
}
__device__ __forceinline__ uint pack_h2(float x, float y) {
    __half2 h = __floats2half2_rn(x, y);
    return *(uint*)&h;
}
__device__ __forceinline__ void cp16g(void* smem, const void* gmem) {
    uint a = smem_u32(smem);
    asm volatile("cp.async.cg.shared.global [%0], [%1], 16;" :: "r"(a), "l"(gmem));
}
__device__ __forceinline__ void cp_commit() { asm volatile("cp.async.commit_group;"); }
template <int N> __device__ __forceinline__ void cp_wait() {
    asm volatile("cp.async.wait_group %0;" :: "n"(N));
}

// ============ K0: fp16 basis gBz[t][80] ============
__global__ void btsplit_kernel() {
    int idx = blockIdx.x * blockDim.x + threadIdx.x;
    if (idx >= L_ * KPZ) return;
    int k = idx % KPZ, t = idx / KPZ;
    float v = 0.f;
    if (k == 0) v = 1.0f;
    else if (k < NC) {
        int f = (k + 1) >> 1;
        int ph = (f * t) & (L_ - 1);
        float s, c;
        sincospif((float)ph * (1.0f / 1024.0f), &s, &c);
        v = (k & 1) ? c : s;
    }
    gBz[idx] = __float2half(v);
}

// ============ K1: 64-pt DFTs -> fp16 coeffs (direct), head-mean subtracted ====
__global__ __launch_bounds__(288) void coeff_kernel(const float* __restrict__ q,
                                                    const float* __restrict__ kin) {
    int bs = blockIdx.x;
    int b  = bs >> 11;
    int s  = bs & (L_ - 1);

    __shared__ float sq[E_], sk[E_];
    __shared__ float twc[64], tws[64];
    __shared__ float A[H_][NC];

    int tid = threadIdx.x;
    for (int i = tid; i < E_; i += blockDim.x) {
        sq[i] = q[(size_t)bs * E_ + i];
        sk[i] = kin[(size_t)bs * E_ + i];
    }
    if (tid < 64) {
        float ss, cc;
        sincospif((float)tid * (1.0f / 32.0f), &ss, &cc);
        twc[tid] = cc; tws[tid] = ss;
    }
    __syncthreads();

    if (tid < H_ * 33) {
        int h = tid / 33, f = tid % 33;
        const float* qh = sq + h * D_;
        const float* kh = sk + h * D_;
        float Qr = 0.f, Qi = 0.f, Kr = 0.f, Ki = 0.f;
#pragma unroll 8
        for (int j = 0; j < 64; j++) {
            int m = (f * j) & 63;
            float c = twc[m], sn = tws[m];
            float qq = qh[j], kk2 = kh[j];
            Qr = fmaf(qq, c, Qr);  Qi = fmaf(-qq, sn, Qi);
            Kr = fmaf(kk2, c, Kr); Ki = fmaf(-kk2, sn, Ki);
        }
        float Xr = Qr * Kr + Qi * Ki;
        float Xi = Qi * Kr - Qr * Ki;
        if (f == 0) {
            A[h][0] = Xr * (1.0f / 2048.0f);
        } else {
            A[h][2 * f - 1] =  Xr * (1.0f / 1024.0f);
            A[h][2 * f]     = -Xi * (1.0f / 1024.0f);
        }
    }
    __syncthreads();

    for (int idx = tid; idx < H_ * KPZ; idx += blockDim.x) {
        int h = idx / KPZ, kk = idx % KPZ;
        float val = 0.f;
        if (kk < NC) {
            float m = 0.f;
#pragma unroll
            for (int hh = 0; hh < H_; hh++) m += A[hh][kk];
            val = A[h][kk] - m * (1.0f / H_);
        }
        gCz[((size_t)(b * H_ + h) * L_ + s) * KPZ + kk] = __float2half(val);
    }
}

// ============ K2: fp16 mma corr GEMM + tile-softmax -> fp16 P (coalesced) =====
// grid (16 t, 16 s, 16 bh), 256 thr, CTA 128x128, single K chunk of 80.
#define PCHZ 88
#define PSTLD 136
__global__ __launch_bounds__(256) void z_mma_kernel() {
    int bh    = blockIdx.z;
    int sbase = blockIdx.y * 128;
    int tbase = blockIdx.x * 128;

    __shared__ __align__(16) char zsm[2 * 128 * PCHZ * 2];  // 45 KB: A/B, later Pst
    __shared__ float rmx[128][5];
    __shared__ float zsh2[128][5];

    __half* As  = (__half*)zsm;
    __half* Bts = As + 128 * PCHZ;
    __half* Pst = (__half*)zsm;          // [128 s][PSTLD] after mainloop

    int tid = threadIdx.x;
    int lane = tid & 31, wid = tid >> 5;
    int g = lane >> 2, tg = lane & 3;
    int mat = lane >> 3, mr = lane & 7;
    int wm = wid >> 2, wn = wid & 3;        // warp tile m64 n32

    float4 acc[4][4];
#pragma unroll
    for (int i = 0; i < 4; i++)
#pragma unroll
        for (int j = 0; j < 4; j++) acc[i][j] = make_float4(0.f, 0.f, 0.f, 0.f);

    int srow = tid >> 1, spart = tid & 1;
    const __half* aG = gCz + ((size_t)bh * L_ + sbase + srow) * KPZ;
    const __half* bG = gBz + (size_t)(tbase + srow) * KPZ;

#pragma unroll
    for (int j = 0; j < 5; j++) {
        int q = spart * 5 + j;
        cp16g(As + srow * PCHZ + q * 8, aG + q * 8);
        cp16g(Bts + srow * PCHZ + q * 8, bG + q * 8);
    }
    cp_commit();
    cp_wait<0>();
    __syncthreads();

#pragma unroll
    for (int ks = 0; ks < 5; ks++) {
        int kofs = ks * 16;
        uint a[4][4], bb[4][2];
#pragma unroll
        for (int mi = 0; mi < 4; mi++) {
            int row = wm * 64 + mi * 16 + (mat & 1) * 8 + mr;
            int col = kofs + (mat >> 1) * 8;
            ldsm_x4(a[mi][0], a[mi][1], a[mi][2], a[mi][3], &As[row * PCHZ + col]);
        }
#pragma unroll
        for (int nj = 0; nj < 2; nj++) {
            int row = wn * 32 + nj * 16 + (mat >> 1) * 8 + mr;
            int col = kofs + (mat & 1) * 8;
            ldsm_x4(bb[2 * nj][0], bb[2 * nj][1], bb[2 * nj + 1][0], bb[2 * nj + 1][1],
                    &Bts[row * PCHZ + col]);
        }
#pragma unroll
        for (int mi = 0; mi < 4; mi++)
#pragma unroll
            for (int ni = 0; ni < 4; ni++)
                mma_fp16(acc[mi][ni], a[mi][0], a[mi][1], a[mi][2], a[mi][3],
                         bb[ni][0], bb[ni][1]);
    }

    // ---- epilogue: row-tile max (acc only; As/Bts dead after this barrier) ----
#pragma unroll
    for (int mi = 0; mi < 4; mi++) {
        float m0 = -1e30f, m1 = -1e30f;
#pragma unroll
        for (int ni = 0; ni < 4; ni++) {
            float4 c = acc[mi][ni];
            m0 = fmaxf(m0, fmaxf(c.x, c.y));
            m1 = fmaxf(m1, fmaxf(c.z, c.w));
        }
        m0 = fmaxf(m0, __shfl_xor_sync(0xffffffffu, m0, 1));
        m0 = fmaxf(m0, __shfl_xor_sync(0xffffffffu, m0, 2));
        m1 = fmaxf(m1, __shfl_xor_sync(0xffffffffu, m1, 1));
        m1 = fmaxf(m1, __shfl_xor_sync(0xffffffffu, m1, 2));
        if (tg == 0) {
            rmx[wm * 64 + mi * 16 + g][wn]     = m0;
            rmx[wm * 64 + mi * 16 + g + 8][wn] = m1;
        }
    }
    __syncthreads();
    if (tid < 128) {
        float mm = fmaxf(fmaxf(rmx[tid][0], rmx[tid][1]), fmaxf(rmx[tid][2], rmx[tid][3]));
        rmx[tid][4] = mm;
        g_E[((size_t)blockIdx.x * BH + bh) * L_ + sbase + tid] = mm;
    }
    __syncthreads();

    const float LOG2E = 1.4426950408889634f;
    float zl[4][2];
#pragma unroll
    for (int mi = 0; mi < 4; mi++) { zl[mi][0] = 0.f; zl[mi][1] = 0.f; }
#pragma unroll
    for (int mi = 0; mi < 4; mi++) {
        int lr0 = wm * 64 + mi * 16 + g;
        float mkA = rmx[lr0][4] * LOG2E, mkB = rmx[lr0 + 8][4] * LOG2E;
#pragma unroll
        for (int ni = 0; ni < 4; ni++) {
            int tc = wn * 32 + ni * 8 + 2 * tg;
            float4 c = acc[mi][ni];
            float e0 = exp2f(fmaf(c.x, LOG2E, -mkA));
            float e1 = exp2f(fmaf(c.y, LOG2E, -mkA));
            float e2 = exp2f(fmaf(c.z, LOG2E, -mkB));
            float e3 = exp2f(fmaf(c.w, LOG2E, -mkB));
            zl[mi][0] += e0 + e1;
            zl[mi][1] += e2 + e3;
            *(uint*)&Pst[lr0 * PSTLD + tc]       = pack_h2(e0, e1);
            *(uint*)&Pst[(lr0 + 8) * PSTLD + tc] = pack_h2(e2, e3);
        }
    }
    // race-free rowsum
#pragma unroll
    for (int mi = 0; mi < 4; mi++)
#pragma unroll
        for (int hh = 0; hh < 2; hh++) {
            float v = zl[mi][hh];
            v += __shfl_xor_sync(0xffffffffu, v, 1);
            v += __shfl_xor_sync(0xffffffffu, v, 2);
            if (tg == 0) zsh2[wm * 64 + mi * 16 + g + hh * 8][wn] = v;
        }
    __syncthreads();
    if (tid < 128)
        g_Zp[((size_t)blockIdx.x * BH + bh) * L_ + sbase + tid] =
            (zsh2[tid][0] + zsh2[tid][1]) + (zsh2[tid][2] + zsh2[tid][3]);

    // coalesced P store: thread -> (row, 64-half segment)
    {
        const size_t Pb = (size_t)bh * L_ * L_;
        int row = tid >> 1, seg = tid & 1;
        const __half* src = &Pst[row * PSTLD + seg * 64];
        __half* gp = &g_Pf[Pb + (size_t)(sbase + row) * L_ + tbase + seg * 64];
#pragma unroll
        for (int i = 0; i < 8; i++)
            *(uint4*)(gp + i * 8) = *(const uint4*)(src + i * 8);
    }
}

// ============ K2b: Z = sum_tt e^E * Zp -> W[tt] = e^E / Z ============
__global__ void zcombine_kernel() {
    int i = blockIdx.x * blockDim.x + threadIdx.x;
    if (i >= BH * L_) return;
    float ee[16];
    float z = 0.f;
#pragma unroll
    for (int tt = 0; tt < 16; tt++) {
        ee[tt] = __expf(g_E[(size_t)tt * (BH * L_) + i]);
        z += ee[tt] * g_Zp[(size_t)tt * (BH * L_) + i];
    }
    float iz = 1.0f / z;
#pragma unroll
    for (int tt = 0; tt < 16; tt++)
        g_W[(size_t)tt * (BH * L_) + i] = ee[tt] * iz;
}

// ============ K3: single-term fp16 out GEMM, full-s, direct scattered out ====
// grid (16 l, 16 bh), 256 thr, CTA 128(l) x 64(d), 64 chunks of 32 s
#define LDA3 136
#define LDV3 72
#define PBUF (32 * LDA3)
#define VBUF (32 * LDV3)
__global__ __launch_bounds__(256) void out_mma_kernel(const float* __restrict__ values,
                                                      float* __restrict__ out) {
    int bh = blockIdx.y;
    int b  = bh >> 3, h = bh & 7;
    int lbase = blockIdx.x * 128;

    __shared__ __align__(16) char smemraw[33280];
    __half* Pf0 = (__half*)smemraw;                  // [2][PBUF]
    __half* Vh0 = Pf0 + 2 * PBUF;                    // [2][VBUF]
    float* osb = (float*)smemraw;                    // [128][65] after loop

    int tid = threadIdx.x;
    int lane = tid & 31, wid = tid >> 5;
    int g = lane >> 2, tg = lane & 3;
    int mat = lane >> 3, mr = lane & 7;
    int wm = wid >> 1, wn = wid & 1;

    float4 acc[2][4];
#pragma unroll
    for (int i = 0; i < 2; i++)
#pragma unroll
        for (int j = 0; j < 4; j++) acc[i][j] = make_float4(0.f, 0.f, 0.f, 0.f);

    const size_t Pb = (size_t)bh * L_ * L_;
    const float* vptr = values + (size_t)b * L_ * E_ + h * D_;
    const float* Wbase = &g_W[((size_t)blockIdx.x * BH + bh) * L_];

    int psc0 = tid >> 4, pc8_0 = (tid & 15) * 8;
    int vsc = tid >> 3, vdq = tid & 7;

    // ---- prologue: chunk 0 ----
    {
#pragma unroll
        for (int it = 0; it < 2; it++) {
            int sc = psc0 + it * 16;
            cp16g(&Pf0[sc * LDA3 + pc8_0], &g_Pf[Pb + (size_t)sc * L_ + lbase + pc8_0]);
        }
        cp_commit();
        float iz = Wbase[vsc];
#pragma unroll
        for (int j = 0; j < 2; j++) {
            int d4 = vdq + 8 * j;
            float4 v4 = *(const float4*)&vptr[(size_t)vsc * E_ + d4 * 4];
            *(uint2*)&Vh0[vsc * LDV3 + d4 * 4] =
                make_uint2(pack_h2(v4.x * iz, v4.y * iz), pack_h2(v4.z * iz, v4.w * iz));
        }
    }

    for (int sch = 0; sch < 64; sch++) {
        int buf = sch & 1;
        float4 vr[2];
        float vizn = 0.f;
        if (sch < 63) {
            int nb = (sch + 1) & 1;
            int nsb = (sch + 1) * 32;
#pragma unroll
            for (int it = 0; it < 2; it++) {
                int sc = psc0 + it * 16;
                cp16g(&Pf0[nb * PBUF + sc * LDA3 + pc8_0],
                      &g_Pf[Pb + (size_t)(nsb + sc) * L_ + lbase + pc8_0]);
            }
            cp_commit();
            vizn = Wbase[nsb + vsc];
            vr[0] = *(const float4*)&vptr[(size_t)(nsb + vsc) * E_ + vdq * 4];
            vr[1] = *(const float4*)&vptr[(size_t)(nsb + vsc) * E_ + vdq * 4 + 32];
            cp_wait<1>();
        } else {
            cp_wait<0>();
        }
        __syncthreads();

        const __half* Pf = Pf0 + buf * PBUF;
        const __half* Vh = Vh0 + buf * VBUF;

#pragma unroll
        for (int ks = 0; ks < 2; ks++) {
            int kofs = ks * 16;
            uint ap[2][4], vv[4][2];
            {
                int row = kofs + (mat >> 1) * 8 + mr;
#pragma unroll
                for (int mi = 0; mi < 2; mi++) {
                    int col = wm * 32 + mi * 16 + (mat & 1) * 8;
                    ldsm_x4_t(ap[mi][0], ap[mi][1], ap[mi][2], ap[mi][3], &Pf[row * LDA3 + col]);
                }
            }
            {
                int row = kofs + (mat & 1) * 8 + mr;
#pragma unroll
                for (int nj = 0; nj < 2; nj++) {
                    int col = wn * 32 + nj * 16 + (mat >> 1) * 8;
                    ldsm_x4_t(vv[2 * nj][0], vv[2 * nj][1], vv[2 * nj + 1][0], vv[2 * nj + 1][1],
                              &Vh[row * LDV3 + col]);
                }
            }
#pragma unroll
            for (int mi = 0; mi < 2; mi++)
#pragma unroll
                for (int ni = 0; ni < 4; ni++)
                    mma_fp16(acc[mi][ni], ap[mi][0], ap[mi][1], ap[mi][2], ap[mi][3],
                             vv[ni][0], vv[ni][1]);
        }

        if (sch < 63) {   // STS prefetched scaled V into alternate buffer
            int nb = (sch + 1) & 1;
#pragma unroll
            for (int j = 0; j < 2; j++) {
                int d4 = vdq + 8 * j;
                float4 v4 = vr[j];
                *(uint2*)&Vh0[nb * VBUF + vsc * LDV3 + d4 * 4] =
                    make_uint2(pack_h2(v4.x * vizn, v4.y * vizn),
                               pack_h2(v4.z * vizn, v4.w * vizn));
            }
        }
        __syncthreads();
    }

    // accums -> osb[l][65]
#pragma unroll
    for (int mi = 0; mi < 2; mi++) {
        int l0 = wm * 32 + mi * 16 + g;
#pragma unroll
        for (int ni = 0; ni < 4; ni++) {
            int d0 = wn * 32 + ni * 8 + 2 * tg;
            float4 c = acc[mi][ni];
            osb[l0 * 65 + d0]           = c.x;
            osb[l0 * 65 + d0 + 1]       = c.y;
            osb[(l0 + 8) * 65 + d0]     = c.z;
            osb[(l0 + 8) * 65 + d0 + 1] = c.w;
        }
    }
    __syncthreads();
    {   // faithful reshape: Vt[b,h,dd,l] -> out[b][dd*32+h*4+(l>>9)][l&511]
        int l1     = lbase >> 9;
        int l0base = lbase & 511;
        int dq = tid >> 2, lq = tid & 3;
        float* op = out + ((size_t)b * 2048 + dq * 32 + h * 4 + l1) * 512 + l0base;
#pragma unroll
        for (int j = 0; j < 8; j++) {
            int l4 = lq + 4 * j;
            float4 w;
            w.x = osb[(l4 * 4 + 0) * 65 + dq];
            w.y = osb[(l4 * 4 + 1) * 65 + dq];
            w.z = osb[(l4 * 4 + 2) * 65 + dq];
            w.w = osb[(l4 * 4 + 3) * 65 + dq];
            *(float4*)&op[l4 * 4] = w;
        }
    }
}

// ============ launch ============
extern "C" void kernel_launch(void* const* d_in, const int* in_sizes, int n_in,
                              void* d_out, int out_size) {
    (void)in_sizes; (void)n_in; (void)out_size;
    const float* q = (const float*)d_in[0];
    const float* k = (const float*)d_in[1];
    const float* v = (const float*)d_in[2];
    float* out = (float*)d_out;

    btsplit_kernel<<<(L_ * KPZ + 255) / 256, 256>>>();
    coeff_kernel<<<B_ * L_, 288>>>(q, k);
    z_mma_kernel<<<dim3(16, 16, BH), 256>>>();
    zcombine_kernel<<<(BH * L_ + 255) / 256, 256>>>();
    out_mma_kernel<<<dim3(16, BH), 256>>>(v, out);
}